// round 14
// baseline (speedup 1.0000x reference)
#include <cuda_runtime.h>
#include <cuda_fp16.h>

// Dense backward image warp, bilinear, fp32 in/out.
// image: [B, H, W, 3], flow: [B, H, W, 2] (y, x), out: [B, H, W, 3]
//
// R14: R13 (fp16 smem tile, LDS.64 taps, 4 CTAs/SM) with the staging loop
// fixed back to R9's fully-coalesced channel-split form:
//   thread owns a fixed (pixel-in-row, channel) float; consecutive tid =
//   consecutive gmem float (4-B lane stride -> 1 line/request) and writes
//   one fp16 via STS.16 into the padded-pixel tile.
// This removes the 3x scalar LDG.32 @ 12-B stride staging (~1100 wf/block,
// 40% of L1 cycles in R13).

#define Bn 16
#define Hn 720
#define Wn 1280

#define TILE_W 64
#define TILE_H 30
#define RAD    4
#define TC     (TILE_W + 2 * RAD + 2)   // 74 tile cols
#define TR     (TILE_H + 2 * RAD + 2)   // 40 tile rows
#define NTHR   480                       // 16 thr/row * 30 rows

struct __align__(8) hpix { __half2 a; __half2 b; };  // c0,c1 | c2,pad

__global__ __launch_bounds__(NTHR, 4) void backwarp_kernel(
    const float* __restrict__ img,
    const float* __restrict__ flow,
    float* __restrict__ out)
{
    __shared__ hpix s_px[TR * TC];   // 23,680 B

    const int HW  = Hn * Wn;
    const int tid = threadIdx.x;
    const int b   = blockIdx.z;
    const int x0  = blockIdx.x * TILE_W;
    const int y0  = blockIdx.y * TILE_H;
    const int ox  = x0 - RAD;
    const int oy  = y0 - RAD;

    const float* __restrict__ imgb = img + (size_t)b * HW * 3;

    // ---- Stage tile: channel-split, fully coalesced LDG + STS.16 ----
    // 444 threads = 2 rows x 222 floats; 20 iterations of 2 rows each.
    {
        const int S_ROW = TC * 3;                  // 222 floats per tile row
        if (tid < 2 * S_ROW) {
            const int half = (tid >= S_ROW) ? 1 : 0;
            const int f0   = tid - half * S_ROW;   // 0..221 (consecutive!)
            const int tp   = f0 / 3;               // pixel in row (fixed)
            const int ch   = f0 - tp * 3;          // channel      (fixed)
            const int gc   = min(max(ox + tp, 0), Wn - 1);
            const int gbase = gc * 3 + ch;         // gmem float offset (fixed)
            const int sbase = tp * 4 + ch;         // smem half offset  (fixed)
            __half* __restrict__ s_h = reinterpret_cast<__half*>(s_px);
            #pragma unroll 4
            for (int rr = half; rr < TR; rr += 2) {
                int gr = min(max(oy + rr, 0), Hn - 1);
                float v = __ldg(imgb + (size_t)gr * (Wn * 3) + gbase);
                s_h[rr * (TC * 4) + sbase] = __float2half_rn(v);
            }
        }
    }
    __syncthreads();

    // ---- Main: 4 consecutive x pixels per thread (unchanged from R13) ----
    const int row = tid >> 4;          // 0..29
    const int xg  = (tid & 15) * 4;    // 0..60
    const int gy  = y0 + row;
    const int gx0 = x0 + xg;
    const size_t pixbase = (size_t)b * HW + (size_t)gy * Wn + gx0;

    // flow: 8 floats = 2x float4 (16-B aligned)
    const float4 f01 = __ldcs(reinterpret_cast<const float4*>(flow + pixbase * 2));
    const float4 f23 = __ldcs(reinterpret_cast<const float4*>(flow + pixbase * 2 + 4));

    const float fyv[4] = { f01.x, f01.z, f23.x, f23.z };
    const float fxv[4] = { f01.y, f01.w, f23.y, f23.w };

    float res[4][3];

    #pragma unroll
    for (int i = 0; i < 4; i++) {
        float qy = (float)gy        - fyv[i];
        float qx = (float)(gx0 + i) - fxv[i];

        float flY = fminf(fmaxf(floorf(qy), 0.0f), (float)(Hn - 2));
        float flX = fminf(fmaxf(floorf(qx), 0.0f), (float)(Wn - 2));
        float ay  = fminf(fmaxf(qy - flY, 0.0f), 1.0f);
        float ax  = fminf(fmaxf(qx - flX, 0.0f), 1.0f);

        int iy = (int)flY;
        int ix = (int)flX;
        int ty = iy - oy;
        int tx = ix - ox;

        float tl0, tl1, tl2, tr0, tr1, tr2;
        float bl0, bl1, bl2, br0, br1, br2;

        if ((unsigned)ty < (unsigned)(TR - 1) && (unsigned)tx < (unsigned)(TC - 1)) {
            const hpix ptl = s_px[ty * TC + tx];
            const hpix ptr = s_px[ty * TC + tx + 1];
            const hpix pbl = s_px[ty * TC + tx + TC];
            const hpix pbr = s_px[ty * TC + tx + TC + 1];
            float2 v;
            v = __half22float2(ptl.a); tl0 = v.x; tl1 = v.y; tl2 = __low2float(ptl.b);
            v = __half22float2(ptr.a); tr0 = v.x; tr1 = v.y; tr2 = __low2float(ptr.b);
            v = __half22float2(pbl.a); bl0 = v.x; bl1 = v.y; bl2 = __low2float(pbl.b);
            v = __half22float2(pbr.a); br0 = v.x; br1 = v.y; br2 = __low2float(pbr.b);
        } else {
            // |flow| > RAD: ~1.3e-4 per pixel — fp32 global fallback
            const float* pt = imgb + ((size_t)iy * Wn + ix) * 3;
            const float* pb = pt + Wn * 3;
            tl0 = pt[0]; tl1 = pt[1]; tl2 = pt[2];
            tr0 = pt[3]; tr1 = pt[4]; tr2 = pt[5];
            bl0 = pb[0]; bl1 = pb[1]; bl2 = pb[2];
            br0 = pb[3]; br1 = pb[4]; br2 = pb[5];
        }

        float top0 = fmaf(ax, tr0 - tl0, tl0);
        float top1 = fmaf(ax, tr1 - tl1, tl1);
        float top2 = fmaf(ax, tr2 - tl2, tl2);
        float bot0 = fmaf(ax, br0 - bl0, bl0);
        float bot1 = fmaf(ax, br1 - bl1, bl1);
        float bot2 = fmaf(ax, br2 - bl2, bl2);

        res[i][0] = fmaf(ay, bot0 - top0, top0);
        res[i][1] = fmaf(ay, bot1 - top1, top1);
        res[i][2] = fmaf(ay, bot2 - top2, top2);
    }

    // 12 contiguous floats -> 3x float4 streaming stores (16-B aligned)
    float* __restrict__ op = out + pixbase * 3;
    __stcs(reinterpret_cast<float4*>(op) + 0,
           make_float4(res[0][0], res[0][1], res[0][2], res[1][0]));
    __stcs(reinterpret_cast<float4*>(op) + 1,
           make_float4(res[1][1], res[1][2], res[2][0], res[2][1]));
    __stcs(reinterpret_cast<float4*>(op) + 2,
           make_float4(res[2][2], res[3][0], res[3][1], res[3][2]));
}

extern "C" void kernel_launch(void* const* d_in, const int* in_sizes, int n_in,
                              void* d_out, int out_size)
{
    const float* image = (const float*)d_in[0];  // [B,H,W,3]
    const float* flow  = (const float*)d_in[1];  // [B,H,W,2]
    float* out         = (float*)d_out;          // [B,H,W,3]

    dim3 grid(Wn / TILE_W, Hn / TILE_H, Bn);     // (20, 24, 16)
    backwarp_kernel<<<grid, NTHR>>>(image, flow, out);
}

// round 15
// speedup vs baseline: 1.0365x; 1.0365x over previous
#include <cuda_runtime.h>
#include <cuda_fp16.h>

// Dense backward image warp, bilinear, fp32 in/out.
// image: [B, H, W, 3], flow: [B, H, W, 2] (y, x), out: [B, H, W, 3]
//
// R15: latency-oriented pass over R13/R14 (fp16 smem tile, LDS.64 taps,
// 4 CTAs/SM):
//  - flow LDG.128s hoisted ABOVE the staging loop: their DRAM latency now
//    overlaps staging + barrier instead of being exposed after it
//  - interior-x blocks stage via 8-B-aligned float2 (LDG.64 + 2xSTS.16),
//    halving staging loop trips (20 -> 10); edge-x blocks keep scalar path
//  - main loop unchanged from R13 (best-known)

#define Bn 16
#define Hn 720
#define Wn 1280

#define TILE_W 64
#define TILE_H 30
#define RAD    4
#define TC     (TILE_W + 2 * RAD + 2)   // 74 tile cols
#define TR     (TILE_H + 2 * RAD + 2)   // 40 tile rows
#define NTHR   480                       // 16 thr/row * 30 rows
#define GRIDX  (Wn / TILE_W)             // 20

struct __align__(8) hpix { __half2 a; __half2 b; };  // c0,c1 | c2,pad

__global__ __launch_bounds__(NTHR, 4) void backwarp_kernel(
    const float* __restrict__ img,
    const float* __restrict__ flow,
    float* __restrict__ out)
{
    __shared__ hpix s_px[TR * TC];   // 23,680 B

    const int HW  = Hn * Wn;
    const int tid = threadIdx.x;
    const int b   = blockIdx.z;
    const int x0  = blockIdx.x * TILE_W;
    const int y0  = blockIdx.y * TILE_H;
    const int ox  = x0 - RAD;
    const int oy  = y0 - RAD;

    const float* __restrict__ imgb = img + (size_t)b * HW * 3;

    // ---- Main-loop thread geometry (needed early for flow prefetch) ----
    const int row = tid >> 4;          // 0..29
    const int xg  = (tid & 15) * 4;    // 0..60
    const int gy  = y0 + row;
    const int gx0 = x0 + xg;
    const size_t pixbase = (size_t)b * HW + (size_t)gy * Wn + gx0;

    // ---- Prefetch flow BEFORE staging: overlaps DRAM latency with the
    //      staging loop and the barrier. 2x LDG.128, 16-B aligned. ----
    const float4 f01 = __ldcs(reinterpret_cast<const float4*>(flow + pixbase * 2));
    const float4 f23 = __ldcs(reinterpret_cast<const float4*>(flow + pixbase * 2 + 4));

    // ---- Stage tile (fp32 -> fp16, padded-pixel layout) ----
    if (blockIdx.x != 0 && blockIdx.x != GRIDX - 1) {
        // Interior-x: no x-clamp anywhere in the tile row; the 222-float row
        // segment is gmem-contiguous and ox*3 is even -> aligned float2.
        // 444 threads = 4 rows x 111 float-pairs; 10 sweeps cover TR=40.
        if (tid < 444) {
            const int row_off = tid / 111;            // 0..3   (fixed)
            const int pr      = tid - row_off * 111;  // 0..110 (fixed)
            const int f0  = 2 * pr;
            const int tp0 = f0 / 3,  ch0 = f0 - tp0 * 3;
            const int tp1 = (f0 + 1) / 3, ch1 = (f0 + 1) - tp1 * 3;
            const int s0  = tp0 * 4 + ch0;            // smem half idx (fixed)
            const int s1  = tp1 * 4 + ch1;
            const float* __restrict__ gseg = imgb + ox * 3 + f0;
            __half* __restrict__ s_h = reinterpret_cast<__half*>(s_px);
            #pragma unroll
            for (int rr = row_off; rr < TR; rr += 4) {
                int gr = min(max(oy + rr, 0), Hn - 1);
                float2 v = __ldg(reinterpret_cast<const float2*>(
                                     gseg + (size_t)gr * (Wn * 3)));
                s_h[rr * (TC * 4) + s0] = __float2half_rn(v.x);
                s_h[rr * (TC * 4) + s1] = __float2half_rn(v.y);
            }
        }
    } else {
        // Edge-x blocks: scalar channel-split path (handles x clamping).
        const int S_ROW = TC * 3;                  // 222 floats per tile row
        if (tid < 2 * S_ROW) {
            const int half = (tid >= S_ROW) ? 1 : 0;
            const int f0   = tid - half * S_ROW;   // 0..221
            const int tp   = f0 / 3;
            const int ch   = f0 - tp * 3;
            const int gc   = min(max(ox + tp, 0), Wn - 1);
            const int gbase = gc * 3 + ch;
            const int sbase = tp * 4 + ch;
            __half* __restrict__ s_h = reinterpret_cast<__half*>(s_px);
            #pragma unroll 4
            for (int rr = half; rr < TR; rr += 2) {
                int gr = min(max(oy + rr, 0), Hn - 1);
                float v = __ldg(imgb + (size_t)gr * (Wn * 3) + gbase);
                s_h[rr * (TC * 4) + sbase] = __float2half_rn(v);
            }
        }
    }
    __syncthreads();

    // ---- Main: 4 consecutive x pixels per thread (unchanged from R13) ----
    const float fyv[4] = { f01.x, f01.z, f23.x, f23.z };
    const float fxv[4] = { f01.y, f01.w, f23.y, f23.w };

    float res[4][3];

    #pragma unroll
    for (int i = 0; i < 4; i++) {
        float qy = (float)gy        - fyv[i];
        float qx = (float)(gx0 + i) - fxv[i];

        float flY = fminf(fmaxf(floorf(qy), 0.0f), (float)(Hn - 2));
        float flX = fminf(fmaxf(floorf(qx), 0.0f), (float)(Wn - 2));
        float ay  = fminf(fmaxf(qy - flY, 0.0f), 1.0f);
        float ax  = fminf(fmaxf(qx - flX, 0.0f), 1.0f);

        int iy = (int)flY;
        int ix = (int)flX;
        int ty = iy - oy;
        int tx = ix - ox;

        float tl0, tl1, tl2, tr0, tr1, tr2;
        float bl0, bl1, bl2, br0, br1, br2;

        if ((unsigned)ty < (unsigned)(TR - 1) && (unsigned)tx < (unsigned)(TC - 1)) {
            const hpix ptl = s_px[ty * TC + tx];
            const hpix ptr = s_px[ty * TC + tx + 1];
            const hpix pbl = s_px[ty * TC + tx + TC];
            const hpix pbr = s_px[ty * TC + tx + TC + 1];
            float2 v;
            v = __half22float2(ptl.a); tl0 = v.x; tl1 = v.y; tl2 = __low2float(ptl.b);
            v = __half22float2(ptr.a); tr0 = v.x; tr1 = v.y; tr2 = __low2float(ptr.b);
            v = __half22float2(pbl.a); bl0 = v.x; bl1 = v.y; bl2 = __low2float(pbl.b);
            v = __half22float2(pbr.a); br0 = v.x; br1 = v.y; br2 = __low2float(pbr.b);
        } else {
            // |flow| > RAD: ~1.3e-4 per pixel — fp32 global fallback
            const float* pt = imgb + ((size_t)iy * Wn + ix) * 3;
            const float* pb = pt + Wn * 3;
            tl0 = pt[0]; tl1 = pt[1]; tl2 = pt[2];
            tr0 = pt[3]; tr1 = pt[4]; tr2 = pt[5];
            bl0 = pb[0]; bl1 = pb[1]; bl2 = pb[2];
            br0 = pb[3]; br1 = pb[4]; br2 = pb[5];
        }

        float top0 = fmaf(ax, tr0 - tl0, tl0);
        float top1 = fmaf(ax, tr1 - tl1, tl1);
        float top2 = fmaf(ax, tr2 - tl2, tl2);
        float bot0 = fmaf(ax, br0 - bl0, bl0);
        float bot1 = fmaf(ax, br1 - bl1, bl1);
        float bot2 = fmaf(ax, br2 - bl2, bl2);

        res[i][0] = fmaf(ay, bot0 - top0, top0);
        res[i][1] = fmaf(ay, bot1 - top1, top1);
        res[i][2] = fmaf(ay, bot2 - top2, top2);
    }

    // 12 contiguous floats -> 3x float4 streaming stores (16-B aligned)
    float* __restrict__ op = out + pixbase * 3;
    __stcs(reinterpret_cast<float4*>(op) + 0,
           make_float4(res[0][0], res[0][1], res[0][2], res[1][0]));
    __stcs(reinterpret_cast<float4*>(op) + 1,
           make_float4(res[1][1], res[1][2], res[2][0], res[2][1]));
    __stcs(reinterpret_cast<float4*>(op) + 2,
           make_float4(res[2][2], res[3][0], res[3][1], res[3][2]));
}

extern "C" void kernel_launch(void* const* d_in, const int* in_sizes, int n_in,
                              void* d_out, int out_size)
{
    const float* image = (const float*)d_in[0];  // [B,H,W,3]
    const float* flow  = (const float*)d_in[1];  // [B,H,W,2]
    float* out         = (float*)d_out;          // [B,H,W,3]

    dim3 grid(GRIDX, Hn / TILE_H, Bn);           // (20, 24, 16)
    backwarp_kernel<<<grid, NTHR>>>(image, flow, out);
}